// round 13
// baseline (speedup 1.0000x reference)
#include <cuda_runtime.h>
#include <math_constants.h>

#define BB 2
#define LL 2048
#define HH 1024
#define NHEAD 16
#define HD 64
#define SOFTMAX_SCALE (1.0f / 32.0f)
#define LOG2E 1.4426950408889634f
#define SCALE2 (SOFTMAX_SCALE * LOG2E)
#define FMIN (-3.402823466e38f)

// Scratch (device globals: allocation-free rule)
__device__ float g_Q[BB * LL * HH];
__device__ float g_K[BB * LL * HH];
__device__ float g_V[BB * LL * HH];
__device__ float g_C[BB * LL * HH];
__device__ float g_X[BB * LL * HH];
__device__ float g_Wq[HH * HH];
__device__ float g_Wk[HH * HH];
__device__ float g_Wv[HH * HH];
__device__ float g_Wo[HH * HH];

// ---------------------------------------------------------------------------
// helpers
// ---------------------------------------------------------------------------
__device__ __forceinline__ unsigned f2tf(float x) {
    unsigned r;
    asm("cvt.rna.tf32.f32 %0, %1;" : "=r"(r) : "f"(x));
    return r;
}
__device__ __forceinline__ float frnd(float x) { return __uint_as_float(f2tf(x)); }

__device__ __forceinline__ float ex2(float x) {
    float r;
    asm("ex2.approx.f32 %0, %1;" : "=f"(r) : "f"(x));
    return r;
}

__device__ __forceinline__ void mma_tf32(float* d, const unsigned* a, const unsigned* b) {
    asm volatile(
        "mma.sync.aligned.m16n8k8.row.col.f32.tf32.tf32.f32 "
        "{%0,%1,%2,%3}, {%4,%5,%6,%7}, {%8,%9}, {%0,%1,%2,%3};"
        : "+f"(d[0]), "+f"(d[1]), "+f"(d[2]), "+f"(d[3])
        : "r"(a[0]), "r"(a[1]), "r"(a[2]), "r"(a[3]), "r"(b[0]), "r"(b[1]));
}

__device__ __forceinline__ void cp16(void* dst_smem, const void* src) {
    unsigned d = (unsigned)__cvta_generic_to_shared(dst_smem);
    asm volatile("cp.async.cg.shared.global [%0], [%1], 16;" :: "r"(d), "l"(src));
}
__device__ __forceinline__ void cp_commit() { asm volatile("cp.async.commit_group;"); }
__device__ __forceinline__ void cp_wait0() { asm volatile("cp.async.wait_group 0;"); }
__device__ __forceinline__ void cp_wait1() { asm volatile("cp.async.wait_group 1;"); }

// ---------------------------------------------------------------------------
// Pre-round inputs to tf32 (RNA) once.
// ---------------------------------------------------------------------------
__device__ __forceinline__ float4 rnd4(float4 v) {
    return make_float4(frnd(v.x), frnd(v.y), frnd(v.z), frnd(v.w));
}

__global__ void __launch_bounds__(256)
preconv_kernel(const float* __restrict__ x, const float* __restrict__ wq,
               const float* __restrict__ wk, const float* __restrict__ wv,
               const float* __restrict__ wo) {
    int i = blockIdx.x * blockDim.x + threadIdx.x;
    int stride = gridDim.x * blockDim.x;
    const int NX = BB * LL * HH / 4;
    const int NW = HH * HH / 4;
    for (int k = i; k < NX; k += stride)
        ((float4*)g_X)[k] = rnd4(((const float4*)x)[k]);
    for (int k = i; k < NW; k += stride) {
        ((float4*)g_Wq)[k] = rnd4(((const float4*)wq)[k]);
        ((float4*)g_Wk)[k] = rnd4(((const float4*)wk)[k]);
        ((float4*)g_Wv)[k] = rnd4(((const float4*)wv)[k]);
        ((float4*)g_Wo)[k] = rnd4(((const float4*)wo)[k]);
    }
}

// ---------------------------------------------------------------------------
// tf32 GEMM: C[4096,1024] = A @ W. Block 128x256, 8 warps, warp tile 64x64
// (LDS/MMA = 1.0). BK=32, 3-stage cp.async (stage 48KB, total 144KB).
// ---------------------------------------------------------------------------
#define GKT 32
#define STG_F 12288   // floats per stage (48KB)

template <bool ROUND>
__device__ __forceinline__ void gemm_body(const float* __restrict__ A,
                                          const float* __restrict__ W,
                                          float* __restrict__ C) {
    extern __shared__ float sm[];

    const int tid = threadIdx.x;
    const int lane = tid & 31;
    const int wid = tid >> 5;
    const int wm = (wid >> 2) * 64;   // 0 or 64
    const int wn = (wid & 3) * 64;    // 0..192
    const int m0 = blockIdx.y * 128;
    const int n0 = blockIdx.x * 256;
    const int r0 = lane >> 2;
    const int j = lane & 3;

    const float* Ap = A + m0 * 1024;
    const float* Wp = W + n0;

    auto issue = [&](int it) {
        const int k0 = it * 32;
        float* As = sm + (it % 3) * STG_F;
        float* Bs = As + 4096;
        // A: 128 rows x 8 chunks = 1024 chunk copies
#pragma unroll
        for (int t = 0; t < 4; t++) {
            int id = tid + t * 256;
            int ra = id >> 3, ca = id & 7;
            cp16(&As[ra * 32 + ((ca ^ (ra & 7)) << 2)],
                 &Ap[ra * 1024 + k0 + (ca << 2)]);
        }
        // B: 32 rows x 64 chunks = 2048 chunk copies
#pragma unroll
        for (int t = 0; t < 8; t++) {
            int id = tid + t * 256;
            int rb = id >> 6, cb = id & 63;
            cp16(&Bs[rb * 256 + ((cb ^ ((rb & 3) << 1)) << 2)],
                 &Wp[(k0 + rb) * 1024 + (cb << 2)]);
        }
        cp_commit();
    };

    float acc[4][8][4];
#pragma unroll
    for (int mt = 0; mt < 4; mt++)
#pragma unroll
        for (int nt = 0; nt < 8; nt++)
#pragma unroll
            for (int i = 0; i < 4; i++) acc[mt][nt][i] = 0.0f;

    issue(0);
    issue(1);

    for (int it = 0; it < GKT; it++) {
        if (it == GKT - 1) cp_wait0(); else cp_wait1();
        __syncthreads();
        if (it + 2 < GKT) issue(it + 2);

        const float* As = sm + (it % 3) * STG_F;
        const float* Bs = As + 4096;

#pragma unroll
        for (int kk = 0; kk < 4; kk++) {
            const int k8 = kk << 3;
            const int pA0 = (((kk << 1) ^ r0) << 2) + j;
            const int pA1 = ((((kk << 1) | 1) ^ r0) << 2) + j;
            unsigned af[4][4], bf[8][2];
#pragma unroll
            for (int mt = 0; mt < 4; mt++) {
                const float* base = As + (wm + mt * 16 + r0) * 32;
                af[mt][0] = __float_as_uint(base[pA0]);
                af[mt][1] = __float_as_uint(base[8 * 32 + pA0]);
                af[mt][2] = __float_as_uint(base[pA1]);
                af[mt][3] = __float_as_uint(base[8 * 32 + pA1]);
            }
#pragma unroll
            for (int nt = 0; nt < 8; nt++) {
                const int bn = wn + nt * 8;
                const int phys = (((((bn + r0) >> 2) ^ (j << 1)) << 2) | (r0 & 3));
                bf[nt][0] = __float_as_uint(Bs[(k8 + j) * 256 + phys]);
                bf[nt][1] = __float_as_uint(Bs[(k8 + 4 + j) * 256 + phys]);
            }
#pragma unroll
            for (int mt = 0; mt < 4; mt++)
#pragma unroll
                for (int nt = 0; nt < 8; nt++)
                    mma_tf32(acc[mt][nt], af[mt], bf[nt]);
        }
    }

#pragma unroll
    for (int mt = 0; mt < 4; mt++) {
        int rr = m0 + wm + mt * 16 + r0;
#pragma unroll
        for (int nt = 0; nt < 8; nt++) {
            int cc = n0 + wn + nt * 8 + (j << 1);
            if (ROUND) {
                *(float2*)&C[rr * 1024 + cc] =
                    make_float2(frnd(acc[mt][nt][0]), frnd(acc[mt][nt][1]));
                *(float2*)&C[(rr + 8) * 1024 + cc] =
                    make_float2(frnd(acc[mt][nt][2]), frnd(acc[mt][nt][3]));
            } else {
                *(float2*)&C[rr * 1024 + cc] =
                    make_float2(acc[mt][nt][0], acc[mt][nt][1]);
                *(float2*)&C[(rr + 8) * 1024 + cc] =
                    make_float2(acc[mt][nt][2], acc[mt][nt][3]);
            }
        }
    }
}

__global__ void __launch_bounds__(256, 1)
gemm_qkv() {
    const float* W = (blockIdx.z == 0) ? g_Wq : (blockIdx.z == 1) ? g_Wk : g_Wv;
    float* C = (blockIdx.z == 0) ? g_Q : (blockIdx.z == 1) ? g_K : g_V;
    gemm_body<true>(g_X, W, C);
}

__global__ void __launch_bounds__(256, 1)
gemm_out(float* __restrict__ out) {
    gemm_body<false>(g_C, g_Wo, out);
}

// ---------------------------------------------------------------------------
// Flash attention (R7 structure), tf32 mma, 2-stage cp.async pipeline.
// Softmax via ex2.approx with log2e folded into the scale.
// Dyn smem: K[2][4096] | V[2][4096] | am[2][64]  (66048 B)
// ---------------------------------------------------------------------------
__global__ void __launch_bounds__(128, 3)
attn_kernel(const float* __restrict__ am) {
    extern __shared__ float sm[];

    const int tid = threadIdx.x;
    const int lane = tid & 31;
    const int w = tid >> 5;
    const int q0 = ((int)gridDim.x - 1 - (int)blockIdx.x) * 64;  // reversed
    const int h = blockIdx.y;
    const int b = blockIdx.z;
    const int bL = b * LL;
    const int r0 = lane >> 2;
    const int j = lane & 3;

    auto issue = [&](int ti) {
        const int k0 = ti * 64;
        const int s = ti & 1;
        float* Ks = sm + s * 4096;
        float* Vs = sm + 8192 + s * 4096;
        float* ams = sm + 16384 + s * 64;
#pragma unroll
        for (int t = 0; t < 8; t++) {
            int id = tid + t * 128;
            int r = id >> 4, c = id & 15;
            const float* gk = &g_K[(bL + k0 + r) * HH + h * HD + (c << 2)];
            const float* gv = &g_V[(bL + k0 + r) * HH + h * HD + (c << 2)];
            cp16(&Ks[r * 64 + ((c ^ (r & 7)) << 2)], gk);
            cp16(&Vs[r * 64 + ((c ^ ((r & 3) << 1)) << 2)], gv);
        }
        if (tid < 16) cp16(&ams[tid << 2], &am[bL + k0 + (tid << 2)]);
        cp_commit();
    };

    // Q fragments (pre-rounded in gmem -> raw bits are valid tf32)
    unsigned qa[8][4];
    const float* Qp = g_Q + (bL + q0 + w * 16) * HH + h * HD;
#pragma unroll
    for (int ks = 0; ks < 8; ks++) {
        qa[ks][0] = __float_as_uint(Qp[r0 * HH + ks * 8 + j]);
        qa[ks][1] = __float_as_uint(Qp[(r0 + 8) * HH + ks * 8 + j]);
        qa[ks][2] = __float_as_uint(Qp[r0 * HH + ks * 8 + j + 4]);
        qa[ks][3] = __float_as_uint(Qp[(r0 + 8) * HH + ks * 8 + j + 4]);
    }
    const float amq0 = am[bL + q0 + w * 16 + r0];
    const float amq1 = am[bL + q0 + w * 16 + r0 + 8];
    const int qi0 = q0 + w * 16 + r0;
    const int qi1 = qi0 + 8;

    float o[8][4] = {};
    float mr0 = -CUDART_INF_F, mr1 = -CUDART_INF_F;
    float l0 = 0.0f, l1 = 0.0f;

    const int ntiles = q0 / 64 + 1;
    issue(0);

    for (int ti = 0; ti < ntiles; ti++) {
        const int k0 = ti * 64;
        cp_wait0();
        __syncthreads();
        if (ti + 1 < ntiles) issue(ti + 1);

        const float* Ks = sm + (ti & 1) * 4096;
        const float* Vs = sm + 8192 + (ti & 1) * 4096;
        const float* ams = sm + 16384 + (ti & 1) * 64;
        const bool interior = (k0 + 64 <= q0);   // future mask identically 0

        // S = Q K^T
        float s[8][4] = {};
#pragma unroll
        for (int ks = 0; ks < 8; ks++) {
            const int pK0 = (((ks << 1) ^ r0) << 2) + j;
            const int pK1 = ((((ks << 1) | 1) ^ r0) << 2) + j;
#pragma unroll
            for (int nt = 0; nt < 8; nt++) {
                unsigned bf[2];
                bf[0] = __float_as_uint(Ks[(nt * 8 + r0) * 64 + pK0]);
                bf[1] = __float_as_uint(Ks[(nt * 8 + r0) * 64 + pK1]);
                mma_tf32(s[nt], qa[ks], bf);
            }
        }

        // Mask (faithful: +FMIN*mask, then scale; log2e folded in) + softmax
        float nm0 = mr0, nm1 = mr1;
        if (interior) {
#pragma unroll
            for (int nt = 0; nt < 8; nt++) {
                float2 ak = *(const float2*)&ams[nt * 8 + (j << 1)];
                float mk0 = 1.f - amq0 * ak.x;
                float mk1 = 1.f - amq0 * ak.y;
                float mk2 = 1.f - amq1 * ak.x;
                float mk3 = 1.f - amq1 * ak.y;
                s[nt][0] = (s[nt][0] + FMIN * mk0) * SCALE2;
                s[nt][1] = (s[nt][1] + FMIN * mk1) * SCALE2;
                s[nt][2] = (s[nt][2] + FMIN * mk2) * SCALE2;
                s[nt][3] = (s[nt][3] + FMIN * mk3) * SCALE2;
                nm0 = fmaxf(nm0, fmaxf(s[nt][0], s[nt][1]));
                nm1 = fmaxf(nm1, fmaxf(s[nt][2], s[nt][3]));
            }
        } else {
#pragma unroll
            for (int nt = 0; nt < 8; nt++) {
                int kc = k0 + nt * 8 + (j << 1);
                float2 ak = *(const float2*)&ams[nt * 8 + (j << 1)];
                float mk00 = fmaxf((kc > qi0) ? 1.f : 0.f, 1.f - amq0 * ak.x);
                float mk01 = fmaxf((kc + 1 > qi0) ? 1.f : 0.f, 1.f - amq0 * ak.y);
                float mk10 = fmaxf((kc > qi1) ? 1.f : 0.f, 1.f - amq1 * ak.x);
                float mk11 = fmaxf((kc + 1 > qi1) ? 1.f : 0.f, 1.f - amq1 * ak.y);
                s[nt][0] = (s[nt][0] + FMIN * mk00) * SCALE2;
                s[nt][1] = (s[nt][1] + FMIN * mk01) * SCALE2;
                s[nt][2] = (s[nt][2] + FMIN * mk10) * SCALE2;
                s[nt][3] = (s[nt][3] + FMIN * mk11) * SCALE2;
                nm0 = fmaxf(nm0, fmaxf(s[nt][0], s[nt][1]));
                nm1 = fmaxf(nm1, fmaxf(s[nt][2], s[nt][3]));
            }
        }
        nm0 = fmaxf(nm0, __shfl_xor_sync(0xffffffffu, nm0, 1));
        nm0 = fmaxf(nm0, __shfl_xor_sync(0xffffffffu, nm0, 2));
        nm1 = fmaxf(nm1, __shfl_xor_sync(0xffffffffu, nm1, 1));
        nm1 = fmaxf(nm1, __shfl_xor_sync(0xffffffffu, nm1, 2));

        float corr0 = ex2(mr0 - nm0);
        float corr1 = ex2(mr1 - nm1);
        mr0 = nm0; mr1 = nm1;

        float rs0 = 0.0f, rs1 = 0.0f;
#pragma unroll
        for (int nt = 0; nt < 8; nt++) {
            s[nt][0] = ex2(s[nt][0] - nm0);
            s[nt][1] = ex2(s[nt][1] - nm0);
            s[nt][2] = ex2(s[nt][2] - nm1);
            s[nt][3] = ex2(s[nt][3] - nm1);
            rs0 += s[nt][0] + s[nt][1];
            rs1 += s[nt][2] + s[nt][3];
        }
        rs0 += __shfl_xor_sync(0xffffffffu, rs0, 1);
        rs0 += __shfl_xor_sync(0xffffffffu, rs0, 2);
        rs1 += __shfl_xor_sync(0xffffffffu, rs1, 1);
        rs1 += __shfl_xor_sync(0xffffffffu, rs1, 2);
        l0 = l0 * corr0 + rs0;
        l1 = l1 * corr1 + rs1;
#pragma unroll
        for (int dt = 0; dt < 8; dt++) {
            o[dt][0] *= corr0; o[dt][1] *= corr0;
            o[dt][2] *= corr1; o[dt][3] *= corr1;
        }

        // O += P @ V : permute P (C-layout -> A-layout) via shfl
#pragma unroll
        for (int nt = 0; nt < 8; nt++) {
            unsigned pc0 = f2tf(s[nt][0]), pc1 = f2tf(s[nt][1]);
            unsigned pc2 = f2tf(s[nt][2]), pc3 = f2tf(s[nt][3]);
            int src = (lane & ~3) | (j >> 1);
            int src2 = src + 2;
            unsigned x0 = __shfl_sync(0xffffffffu, pc0, src);
            unsigned x1 = __shfl_sync(0xffffffffu, pc1, src);
            unsigned y0 = __shfl_sync(0xffffffffu, pc2, src);
            unsigned y1 = __shfl_sync(0xffffffffu, pc3, src);
            unsigned x0b = __shfl_sync(0xffffffffu, pc0, src2);
            unsigned x1b = __shfl_sync(0xffffffffu, pc1, src2);
            unsigned y0b = __shfl_sync(0xffffffffu, pc2, src2);
            unsigned y1b = __shfl_sync(0xffffffffu, pc3, src2);
            unsigned af[4];
            af[0] = (lane & 1) ? x1 : x0;
            af[1] = (lane & 1) ? y1 : y0;
            af[2] = (lane & 1) ? x1b : x0b;
            af[3] = (lane & 1) ? y1b : y0b;
#pragma unroll
            for (int dt = 0; dt < 8; dt++) {
                const int pv = ((((dt << 1) | (r0 >> 2)) ^ (j << 1)) << 2) | (r0 & 3);
                unsigned bf[2];
                bf[0] = __float_as_uint(Vs[(nt * 8 + j) * 64 + pv]);
                bf[1] = __float_as_uint(Vs[(nt * 8 + 4 + j) * 64 + pv]);
                mma_tf32(o[dt], af, bf);
            }
        }
    }

    // Normalize, round (next GEMM consumes as tf32), write ctx
    float inv0 = 1.0f / l0, inv1 = 1.0f / l1;
    float* Cp = g_C + (bL + q0 + w * 16) * HH + h * HD;
#pragma unroll
    for (int dt = 0; dt < 8; dt++) {
        int c = dt * 8 + (j << 1);
        *(float2*)&Cp[r0 * HH + c] =
            make_float2(frnd(o[dt][0] * inv0), frnd(o[dt][1] * inv0));
        *(float2*)&Cp[(r0 + 8) * HH + c] =
            make_float2(frnd(o[dt][2] * inv1), frnd(o[dt][3] * inv1));
    }
}

// ---------------------------------------------------------------------------
extern "C" void kernel_launch(void* const* d_in, const int* in_sizes, int n_in,
                              void* d_out, int out_size) {
    const float* input = (const float*)d_in[0];
    const float* amask = (const float*)d_in[1];
    const float* wq = (const float*)d_in[2];
    const float* wk = (const float*)d_in[3];
    const float* wv = (const float*)d_in[4];
    const float* wo = (const float*)d_in[5];
    float* out = (float*)d_out;

    static bool attr_done = false;
    if (!attr_done) {
        cudaFuncSetAttribute(gemm_qkv, cudaFuncAttributeMaxDynamicSharedMemorySize, 147456);
        cudaFuncSetAttribute(gemm_out, cudaFuncAttributeMaxDynamicSharedMemorySize, 147456);
        cudaFuncSetAttribute(attn_kernel, cudaFuncAttributeMaxDynamicSharedMemorySize, 66048);
        attr_done = true;
    }

    preconv_kernel<<<2048, 256>>>(input, wq, wk, wv, wo);
    gemm_qkv<<<dim3(4, 32, 3), 256, 147456>>>();
    attn_kernel<<<dim3(LL / 64, NHEAD, BB), 128, 66048>>>(amask);
    gemm_out<<<dim3(4, 32), 256, 147456>>>(out);
}

// round 17
// speedup vs baseline: 1.4675x; 1.4675x over previous
#include <cuda_runtime.h>
#include <cuda_fp16.h>
#include <math_constants.h>

#define BB 2
#define LL 2048
#define HH 1024
#define NHEAD 16
#define HD 64
#define SOFTMAX_SCALE (1.0f / 32.0f)
#define LOG2E 1.4426950408889634f
#define SCALE2 (SOFTMAX_SCALE * LOG2E)
#define FMIN (-3.402823466e38f)

// Scratch (device globals: allocation-free rule)
__device__ __half g_Xh[BB * LL * HH];
__device__ __half g_Wqh[HH * HH];   // W^T [n][k], fp16
__device__ __half g_Wkh[HH * HH];
__device__ __half g_Wvh[HH * HH];
__device__ __half g_Woh[HH * HH];
__device__ __half g_Qh[BB * LL * HH];
__device__ __half g_Kh[BB * LL * HH];
__device__ __half g_Vh[BB * LL * HH];
__device__ __half g_Vt[BB * NHEAD * HD * LL];  // [b][h][d][seq]
__device__ __half g_Ch[BB * LL * HH];

// ---------------------------------------------------------------------------
// helpers
// ---------------------------------------------------------------------------
__device__ __forceinline__ float ex2(float x) {
    float r;
    asm("ex2.approx.f32 %0, %1;" : "=f"(r) : "f"(x));
    return r;
}

__device__ __forceinline__ unsigned pack2(float a, float b) {
    __half2 h = __floats2half2_rn(a, b);
    return *(unsigned*)&h;
}

__device__ __forceinline__ void mma_f16(float* d, const unsigned* a, const unsigned* b) {
    asm volatile(
        "mma.sync.aligned.m16n8k16.row.col.f32.f16.f16.f32 "
        "{%0,%1,%2,%3}, {%4,%5,%6,%7}, {%8,%9}, {%0,%1,%2,%3};"
        : "+f"(d[0]), "+f"(d[1]), "+f"(d[2]), "+f"(d[3])
        : "r"(a[0]), "r"(a[1]), "r"(a[2]), "r"(a[3]), "r"(b[0]), "r"(b[1]));
}

__device__ __forceinline__ void cp16(void* dst_smem, const void* src) {
    unsigned d = (unsigned)__cvta_generic_to_shared(dst_smem);
    asm volatile("cp.async.cg.shared.global [%0], [%1], 16;" :: "r"(d), "l"(src));
}
__device__ __forceinline__ void cp_commit() { asm volatile("cp.async.commit_group;"); }
__device__ __forceinline__ void cp_wait0() { asm volatile("cp.async.wait_group 0;"); }
__device__ __forceinline__ void cp_wait1() { asm volatile("cp.async.wait_group 1;"); }

// ---------------------------------------------------------------------------
// preconv: X -> fp16; W -> transposed fp16 [n][k]
// ---------------------------------------------------------------------------
__global__ void __launch_bounds__(256)
round_x(const float* __restrict__ x) {
    int i = blockIdx.x * blockDim.x + threadIdx.x;
    int stride = gridDim.x * blockDim.x;
    const int N4 = BB * LL * HH / 4;
    for (int k = i; k < N4; k += stride) {
        float4 v = ((const float4*)x)[k];
        unsigned lo = pack2(v.x, v.y), hi = pack2(v.z, v.w);
        ((uint2*)g_Xh)[k] = make_uint2(lo, hi);
    }
}

__global__ void __launch_bounds__(256)
transpose_w(const float* __restrict__ wq, const float* __restrict__ wk,
            const float* __restrict__ wv, const float* __restrict__ wo) {
    __shared__ float t[32][33];
    const float* src = (blockIdx.z == 0) ? wq : (blockIdx.z == 1) ? wk
                     : (blockIdx.z == 2) ? wv : wo;
    __half* dst = (blockIdx.z == 0) ? g_Wqh : (blockIdx.z == 1) ? g_Wkh
                : (blockIdx.z == 2) ? g_Wvh : g_Woh;
    const int tx = threadIdx.x & 31;
    const int ty = threadIdx.x >> 5;
    const int k0 = blockIdx.y * 32, n0 = blockIdx.x * 32;
#pragma unroll
    for (int r = ty; r < 32; r += 8)
        t[r][tx] = src[(k0 + r) * HH + n0 + tx];
    __syncthreads();
#pragma unroll
    for (int r = ty; r < 32; r += 8)
        dst[(n0 + r) * HH + k0 + tx] = __float2half_rn(t[tx][r]);
}

// ---------------------------------------------------------------------------
// transpose V: g_Vh[b*LL+seq][h*64+d] -> g_Vt[((b*16+h)*64+d)][seq]
// ---------------------------------------------------------------------------
__global__ void __launch_bounds__(256)
transpose_v() {
    __shared__ __half t[64][72];
    const int s0 = blockIdx.x * 64;
    const int h = blockIdx.y;
    const int b = blockIdx.z;
    const int tid = threadIdx.x;
#pragma unroll
    for (int tt = 0; tt < 8; tt++) {
        int id = tid + tt * 256;
        int r = id >> 5, c2 = id & 31;
        __half2 v = *(const __half2*)&g_Vh[(b * LL + s0 + r) * HH + h * HD + 2 * c2];
        t[2 * c2][r] = __low2half(v);
        t[2 * c2 + 1][r] = __high2half(v);
    }
    __syncthreads();
#pragma unroll
    for (int tt = 0; tt < 8; tt++) {
        int id = tid + tt * 256;
        int dr = id >> 5, c2 = id & 31;
        __half2 o = __halves2half2(t[dr][2 * c2], t[dr][2 * c2 + 1]);
        *(__half2*)&g_Vt[((b * NHEAD + h) * HD + dr) * LL + s0 + 2 * c2] = o;
    }
}

// ---------------------------------------------------------------------------
// fp16 GEMM: C[4096,1024] = A @ W (W^T given [n][k]). Block 128x128, 8 warps,
// warp tile 64x32, BK=32 (2 x k16), 3-stage cp.async. Rows padded to 80B.
// Stage = A 128*80 + B 128*80 = 20480 B; 3 stages = 61440 B.
// ---------------------------------------------------------------------------
#define GKT 32
#define GSTG 20480

template <bool HALF_OUT>
__device__ __forceinline__ void gemm_body(const __half* __restrict__ A,
                                          const __half* __restrict__ WT,
                                          void* __restrict__ Cout) {
    extern __shared__ char smc[];

    const int tid = threadIdx.x;
    const int lane = tid & 31;
    const int wid = tid >> 5;
    const int wm = (wid >> 2) * 64;
    const int wn = (wid & 3) * 32;
    const int m0 = blockIdx.y * 128;
    const int n0 = blockIdx.x * 128;
    const int r0 = lane >> 2;
    const int j = lane & 3;

    auto issue = [&](int it) {
        const int k0 = it * 32;
        char* As = smc + (it % 3) * GSTG;
        char* Bs = As + 10240;
#pragma unroll
        for (int t = 0; t < 2; t++) {
            int id = tid + t * 256;
            int ra = id >> 2, ca = id & 3;
            cp16(As + ra * 80 + ca * 16, &A[(m0 + ra) * 1024 + k0 + ca * 8]);
            cp16(Bs + ra * 80 + ca * 16, &WT[(n0 + ra) * 1024 + k0 + ca * 8]);
        }
        cp_commit();
    };

    float acc[4][4][4];
#pragma unroll
    for (int mt = 0; mt < 4; mt++)
#pragma unroll
        for (int nt = 0; nt < 4; nt++)
#pragma unroll
            for (int i = 0; i < 4; i++) acc[mt][nt][i] = 0.0f;

    issue(0);
    issue(1);

    for (int it = 0; it < GKT; it++) {
        if (it == GKT - 1) cp_wait0(); else cp_wait1();
        __syncthreads();
        if (it + 2 < GKT) issue(it + 2);

        const char* As = smc + (it % 3) * GSTG;
        const char* Bs = As + 10240;

#pragma unroll
        for (int g = 0; g < 2; g++) {
            const int off = 32 * g + 4 * j;
            unsigned af[4][4], bf[4][2];
#pragma unroll
            for (int mt = 0; mt < 4; mt++) {
                const char* base = As + (wm + mt * 16 + r0) * 80 + off;
                af[mt][0] = *(const unsigned*)(base);
                af[mt][1] = *(const unsigned*)(base + 8 * 80);
                af[mt][2] = *(const unsigned*)(base + 16);
                af[mt][3] = *(const unsigned*)(base + 8 * 80 + 16);
            }
#pragma unroll
            for (int nt = 0; nt < 4; nt++) {
                const char* base = Bs + (wn + nt * 8 + r0) * 80 + off;
                bf[nt][0] = *(const unsigned*)(base);
                bf[nt][1] = *(const unsigned*)(base + 16);
            }
#pragma unroll
            for (int mt = 0; mt < 4; mt++)
#pragma unroll
                for (int nt = 0; nt < 4; nt++)
                    mma_f16(acc[mt][nt], af[mt], bf[nt]);
        }
    }

#pragma unroll
    for (int mt = 0; mt < 4; mt++) {
        int rr = m0 + wm + mt * 16 + r0;
#pragma unroll
        for (int nt = 0; nt < 4; nt++) {
            int cc = n0 + wn + nt * 8 + (j << 1);
            if (HALF_OUT) {
                __half* C = (__half*)Cout;
                *(unsigned*)&C[rr * 1024 + cc] = pack2(acc[mt][nt][0], acc[mt][nt][1]);
                *(unsigned*)&C[(rr + 8) * 1024 + cc] = pack2(acc[mt][nt][2], acc[mt][nt][3]);
            } else {
                float* C = (float*)Cout;
                *(float2*)&C[rr * 1024 + cc] = make_float2(acc[mt][nt][0], acc[mt][nt][1]);
                *(float2*)&C[(rr + 8) * 1024 + cc] = make_float2(acc[mt][nt][2], acc[mt][nt][3]);
            }
        }
    }
}

__global__ void __launch_bounds__(256, 2)
gemm_qkv() {
    const __half* W = (blockIdx.z == 0) ? g_Wqh : (blockIdx.z == 1) ? g_Wkh : g_Wvh;
    __half* C = (blockIdx.z == 0) ? g_Qh : (blockIdx.z == 1) ? g_Kh : g_Vh;
    gemm_body<true>(g_Xh, W, C);
}

__global__ void __launch_bounds__(256, 2)
gemm_out(float* __restrict__ out) {
    gemm_body<false>(g_Ch, g_Woh, out);
}

// ---------------------------------------------------------------------------
// Flash attention, fp16 m16n8k16. Block = 64 q rows, 128 threads (4 warps).
// K tile [key][d] 64x128B swizzled; V tile from g_Vt [d][key] 64x128B swizzled.
// P C-fragment maps directly to fp16 A-fragment (no shuffles).
// Dyn smem: K[2][8192] | Vt[2][8192] | am[2][256]  (33280 B)
// ---------------------------------------------------------------------------
__global__ void __launch_bounds__(128, 4)
attn_kernel(const float* __restrict__ am) {
    extern __shared__ char smc[];

    const int tid = threadIdx.x;
    const int lane = tid & 31;
    const int w = tid >> 5;
    const int q0 = ((int)gridDim.x - 1 - (int)blockIdx.x) * 64;  // reversed
    const int h = blockIdx.y;
    const int b = blockIdx.z;
    const int bL = b * LL;
    const int r0 = lane >> 2;
    const int j = lane & 3;

    auto issue = [&](int ti) {
        const int k0 = ti * 64;
        const int s = ti & 1;
        char* Ks = smc + s * 8192;
        char* Vs = smc + 16384 + s * 8192;
        char* ams = smc + 32768 + s * 256;
#pragma unroll
        for (int t = 0; t < 4; t++) {
            int id = tid + t * 128;
            int r = id >> 3, c = id & 7;
            int sw = ((c ^ (r & 7)) << 4);
            cp16(Ks + r * 128 + sw, &g_Kh[(bL + k0 + r) * HH + h * HD + c * 8]);
            cp16(Vs + r * 128 + sw, &g_Vt[((b * NHEAD + h) * HD + r) * LL + k0 + c * 8]);
        }
        if (tid < 16) cp16(ams + tid * 16, &am[bL + k0 + tid * 4]);
        cp_commit();
    };

    // Q fragments: 4 k16 steps x 4 regs (half2 each), from gmem fp16
    unsigned qa[4][4];
    {
        const __half* Qp = g_Qh + (bL + q0 + w * 16) * HH + h * HD;
#pragma unroll
        for (int g = 0; g < 4; g++) {
            qa[g][0] = *(const unsigned*)&Qp[r0 * HH + 16 * g + 2 * j];
            qa[g][1] = *(const unsigned*)&Qp[(r0 + 8) * HH + 16 * g + 2 * j];
            qa[g][2] = *(const unsigned*)&Qp[r0 * HH + 16 * g + 2 * j + 8];
            qa[g][3] = *(const unsigned*)&Qp[(r0 + 8) * HH + 16 * g + 2 * j + 8];
        }
    }
    const float amq0 = am[bL + q0 + w * 16 + r0];
    const float amq1 = am[bL + q0 + w * 16 + r0 + 8];
    const int qi0 = q0 + w * 16 + r0;
    const int qi1 = qi0 + 8;

    float o[8][4] = {};
    float mr0 = -CUDART_INF_F, mr1 = -CUDART_INF_F;
    float l0 = 0.0f, l1 = 0.0f;

    const int ntiles = q0 / 64 + 1;
    issue(0);

    for (int ti = 0; ti < ntiles; ti++) {
        const int k0 = ti * 64;
        cp_wait0();
        __syncthreads();
        if (ti + 1 < ntiles) issue(ti + 1);

        const char* Ks = smc + (ti & 1) * 8192;
        const char* Vs = smc + 16384 + (ti & 1) * 8192;
        const float* ams = (const float*)(smc + 32768 + (ti & 1) * 256);
        const bool interior = (k0 + 64 <= q0);

        // S = Q K^T : 4 k16 x 8 nt
        float s[8][4] = {};
#pragma unroll
        for (int g = 0; g < 4; g++) {
            const int cLo = (2 * g), cHi = (2 * g + 1);
#pragma unroll
            for (int nt = 0; nt < 8; nt++) {
                const char* base = Ks + (nt * 8 + r0) * 128 + 4 * j;
                unsigned bk[2];
                bk[0] = *(const unsigned*)(base + ((cLo ^ r0) << 4));
                bk[1] = *(const unsigned*)(base + ((cHi ^ r0) << 4));
                mma_f16(s[nt], qa[g], bk);
            }
        }

        // Mask (faithful: +FMIN*mask, scale w/ log2e folded) + online softmax
        float nm0 = mr0, nm1 = mr1;
        if (interior) {
#pragma unroll
            for (int nt = 0; nt < 8; nt++) {
                float2 ak = *(const float2*)&ams[nt * 8 + (j << 1)];
                float mk0 = 1.f - amq0 * ak.x;
                float mk1 = 1.f - amq0 * ak.y;
                float mk2 = 1.f - amq1 * ak.x;
                float mk3 = 1.f - amq1 * ak.y;
                s[nt][0] = (s[nt][0] + FMIN * mk0) * SCALE2;
                s[nt][1] = (s[nt][1] + FMIN * mk1) * SCALE2;
                s[nt][2] = (s[nt][2] + FMIN * mk2) * SCALE2;
                s[nt][3] = (s[nt][3] + FMIN * mk3) * SCALE2;
                nm0 = fmaxf(nm0, fmaxf(s[nt][0], s[nt][1]));
                nm1 = fmaxf(nm1, fmaxf(s[nt][2], s[nt][3]));
            }
        } else {
#pragma unroll
            for (int nt = 0; nt < 8; nt++) {
                int kc = k0 + nt * 8 + (j << 1);
                float2 ak = *(const float2*)&ams[nt * 8 + (j << 1)];
                float mk00 = fmaxf((kc > qi0) ? 1.f : 0.f, 1.f - amq0 * ak.x);
                float mk01 = fmaxf((kc + 1 > qi0) ? 1.f : 0.f, 1.f - amq0 * ak.y);
                float mk10 = fmaxf((kc > qi1) ? 1.f : 0.f, 1.f - amq1 * ak.x);
                float mk11 = fmaxf((kc + 1 > qi1) ? 1.f : 0.f, 1.f - amq1 * ak.y);
                s[nt][0] = (s[nt][0] + FMIN * mk00) * SCALE2;
                s[nt][1] = (s[nt][1] + FMIN * mk01) * SCALE2;
                s[nt][2] = (s[nt][2] + FMIN * mk10) * SCALE2;
                s[nt][3] = (s[nt][3] + FMIN * mk11) * SCALE2;
                nm0 = fmaxf(nm0, fmaxf(s[nt][0], s[nt][1]));
                nm1 = fmaxf(nm1, fmaxf(s[nt][2], s[nt][3]));
            }
        }
        nm0 = fmaxf(nm0, __shfl_xor_sync(0xffffffffu, nm0, 1));
        nm0 = fmaxf(nm0, __shfl_xor_sync(0xffffffffu, nm0, 2));
        nm1 = fmaxf(nm1, __shfl_xor_sync(0xffffffffu, nm1, 1));
        nm1 = fmaxf(nm1, __shfl_xor_sync(0xffffffffu, nm1, 2));

        float corr0 = ex2(mr0 - nm0);
        float corr1 = ex2(mr1 - nm1);
        mr0 = nm0; mr1 = nm1;

        float rs0 = 0.0f, rs1 = 0.0f;
#pragma unroll
        for (int nt = 0; nt < 8; nt++) {
            s[nt][0] = ex2(s[nt][0] - nm0);
            s[nt][1] = ex2(s[nt][1] - nm0);
            s[nt][2] = ex2(s[nt][2] - nm1);
            s[nt][3] = ex2(s[nt][3] - nm1);
            rs0 += s[nt][0] + s[nt][1];
            rs1 += s[nt][2] + s[nt][3];
        }
        rs0 += __shfl_xor_sync(0xffffffffu, rs0, 1);
        rs0 += __shfl_xor_sync(0xffffffffu, rs0, 2);
        rs1 += __shfl_xor_sync(0xffffffffu, rs1, 1);
        rs1 += __shfl_xor_sync(0xffffffffu, rs1, 2);
        l0 = l0 * corr0 + rs0;
        l1 = l1 * corr1 + rs1;
#pragma unroll
        for (int dt = 0; dt < 8; dt++) {
            o[dt][0] *= corr0; o[dt][1] *= corr0;
            o[dt][2] *= corr1; o[dt][3] *= corr1;
        }

        // O += P @ V : P C-frag -> fp16 A-frag directly (no shuffles)
#pragma unroll
        for (int g = 0; g < 4; g++) {
            unsigned af[4];
            af[0] = pack2(s[2 * g][0], s[2 * g][1]);
            af[1] = pack2(s[2 * g][2], s[2 * g][3]);
            af[2] = pack2(s[2 * g + 1][0], s[2 * g + 1][1]);
            af[3] = pack2(s[2 * g + 1][2], s[2 * g + 1][3]);
            const int cLo = (2 * g), cHi = (2 * g + 1);
#pragma unroll
            for (int dt = 0; dt < 8; dt++) {
                const char* base = Vs + (dt * 8 + r0) * 128 + 4 * j;
                unsigned bv[2];
                bv[0] = *(const unsigned*)(base + ((cLo ^ r0) << 4));
                bv[1] = *(const unsigned*)(base + ((cHi ^ r0) << 4));
                mma_f16(o[dt], af, bv);
            }
        }
    }

    // Normalize, write ctx as fp16 (consumed by out-GEMM)
    float inv0 = 1.0f / l0, inv1 = 1.0f / l1;
    __half* Cp = g_Ch + (bL + q0 + w * 16) * HH + h * HD;
#pragma unroll
    for (int dt = 0; dt < 8; dt++) {
        int c = dt * 8 + (j << 1);
        *(unsigned*)&Cp[r0 * HH + c] = pack2(o[dt][0] * inv0, o[dt][1] * inv0);
        *(unsigned*)&Cp[(r0 + 8) * HH + c] = pack2(o[dt][2] * inv1, o[dt][3] * inv1);
    }
}

// ---------------------------------------------------------------------------
extern "C" void kernel_launch(void* const* d_in, const int* in_sizes, int n_in,
                              void* d_out, int out_size) {
    const float* input = (const float*)d_in[0];
    const float* amask = (const float*)d_in[1];
    const float* wq = (const float*)d_in[2];
    const float* wk = (const float*)d_in[3];
    const float* wv = (const float*)d_in[4];
    const float* wo = (const float*)d_in[5];
    float* out = (float*)d_out;

    static bool attr_done = false;
    if (!attr_done) {
        cudaFuncSetAttribute(gemm_qkv, cudaFuncAttributeMaxDynamicSharedMemorySize, 61440);
        cudaFuncSetAttribute(gemm_out, cudaFuncAttributeMaxDynamicSharedMemorySize, 61440);
        cudaFuncSetAttribute(attn_kernel, cudaFuncAttributeMaxDynamicSharedMemorySize, 33280);
        attr_done = true;
    }

    round_x<<<512, 256>>>(input);
    transpose_w<<<dim3(32, 32, 4), 256>>>(wq, wk, wv, wo);
    gemm_qkv<<<dim3(8, 32, 3), 256, 61440>>>();
    transpose_v<<<dim3(LL / 64, NHEAD, BB), 256>>>();
    attn_kernel<<<dim3(LL / 64, NHEAD, BB), 128, 33280>>>(amask);
    gemm_out<<<dim3(8, 32), 256, 61440>>>(out);
}